// round 1
// baseline (speedup 1.0000x reference)
#include <cuda_runtime.h>

// Problem constants
#define N_E    8192
#define EDIM   256
#define BPOS   8192          // 8 * 32 * 32 positions
#define ZQ_ELEMS 2097152     // 8 * 256 * 32 * 32

// GEMM tiling
#define NSPLIT 2
#define BM 128
#define BN 128
#define BK 32
#define TM 8
#define TN 8
#define THREADS 256
#define BSTRIDE (BN + 4)     // padded B_s row stride (keeps 16B alignment, spreads banks)

// Scratch (static device globals — no allocation allowed)
__device__ float g_pval[NSPLIT * BPOS];
__device__ int   g_pidx[NSPLIT * BPOS];
__device__ int   g_ind[BPOS];
__device__ float g_losspart[8192];

// ---- packed f32x2 helpers ----
__device__ __forceinline__ unsigned long long pk2(float x, float y) {
    unsigned long long r;
    asm("mov.b64 %0, {%1,%2};" : "=l"(r) : "f"(x), "f"(y));
    return r;
}
__device__ __forceinline__ void ffma2(unsigned long long& d,
                                      unsigned long long a,
                                      unsigned long long b) {
    asm("fma.rn.f32x2 %0, %1, %2, %0;" : "+l"(d) : "l"(a), "l"(b));
}
__device__ __forceinline__ float2 up2(unsigned long long v) {
    float2 f;
    asm("mov.b64 {%0,%1}, %2;" : "=f"(f.x), "=f"(f.y) : "l"(v));
    return f;
}

// =====================================================================
// Fused GEMM + row-argmax.
// z: (8, 256, 32, 32) fp32  -> position p = b*1024 + hw, feature d.
//    z[b][d][hw] sits at b*262144 + d*1024 + hw: ALREADY k-major over m.
// W: (8192, 256) fp32 row-major.
// Each block: 128 positions (A resident in SMEM, full K=256),
//             loops over its N-split half in 128-code chunks,
//             K staged in 32-wide W slices.
// =====================================================================
__global__ void __launch_bounds__(THREADS, 1)
gemm_argmax_kernel(const float* __restrict__ z, const float* __restrict__ W) {
    extern __shared__ float smem[];
    float* A_s  = smem;                         // [256][128]
    float* B_s  = A_s + EDIM * BM;              // [32][BSTRIDE]
    float* sval = B_s + BK * BSTRIDE;           // [128]
    int*   sidx = (int*)(sval + BM);            // [128]

    const int t     = threadIdx.x;
    const int mtile = blockIdx.x;               // 0..63
    const int split = blockIdx.y;               // 0..NSPLIT-1
    const int m0    = mtile * BM;
    const int b     = m0 >> 10;
    const int hw0   = m0 & 1023;
    const float* zbase = z + b * (EDIM * 1024) + hw0;

    // Load A tile: A_s[k][m] = z[b][k][hw0+m]  (coalesced float4, conflict-free)
    #pragma unroll
    for (int it = 0; it < (EDIM * BM / 4) / THREADS; it++) {
        int j  = t + it * THREADS;              // 0 .. 8191
        int k  = j >> 5;
        int c4 = j & 31;
        float4 v = *(const float4*)(zbase + k * 1024 + c4 * 4);
        *(float4*)(A_s + k * BM + c4 * 4) = v;
    }
    if (t < BM) { sval[t] = -3.4e38f; sidx[t] = 0; }
    __syncthreads();

    const int tx = t & 15;                      // code direction (16)
    const int ty = t >> 4;                      // row direction (16)
    const int n_split0 = split * (N_E / NSPLIT);

    for (int nc = 0; nc < (N_E / NSPLIT) / BN; nc++) {
        const int n0 = n_split0 + nc * BN;

        unsigned long long acc[TM][TN / 2];
        #pragma unroll
        for (int i = 0; i < TM; i++)
            #pragma unroll
            for (int j = 0; j < TN / 2; j++) acc[i][j] = 0ULL;

        for (int ks = 0; ks < EDIM / BK; ks++) {
            __syncthreads();                    // previous slice consumed
            // Stage W slice: B_s[k][n] = W[n0+n][ks*32+k]
            #pragma unroll
            for (int r = 0; r < 4; r++) {
                int j  = t + r * THREADS;       // 0..1023
                int n  = j >> 3;
                int k4 = j & 7;
                float4 v = *(const float4*)(W + (n0 + n) * EDIM + ks * BK + k4 * 4);
                int k = k4 * 4;
                B_s[(k + 0) * BSTRIDE + n] = v.x;
                B_s[(k + 1) * BSTRIDE + n] = v.y;
                B_s[(k + 2) * BSTRIDE + n] = v.z;
                B_s[(k + 3) * BSTRIDE + n] = v.w;
            }
            __syncthreads();

            const float* Ab = A_s + ks * BK * BM + ty * TM;
            const float* Bb = B_s + tx * TN;
            #pragma unroll
            for (int k = 0; k < BK; k++) {
                float4 a0 = *(const float4*)(Ab + k * BM);
                float4 a1 = *(const float4*)(Ab + k * BM + 4);
                float4 b0 = *(const float4*)(Bb + k * BSTRIDE);
                float4 b1 = *(const float4*)(Bb + k * BSTRIDE + 4);
                unsigned long long bp0 = pk2(b0.x, b0.y);
                unsigned long long bp1 = pk2(b0.z, b0.w);
                unsigned long long bp2 = pk2(b1.x, b1.y);
                unsigned long long bp3 = pk2(b1.z, b1.w);
                float av[TM] = {a0.x, a0.y, a0.z, a0.w, a1.x, a1.y, a1.z, a1.w};
                #pragma unroll
                for (int i = 0; i < TM; i++) {
                    unsigned long long ap = pk2(av[i], av[i]);
                    ffma2(acc[i][0], ap, bp0);
                    ffma2(acc[i][1], ap, bp1);
                    ffma2(acc[i][2], ap, bp2);
                    ffma2(acc[i][3], ap, bp3);
                }
            }
        }

        // Argmax epilogue for this 128-code chunk.
        #pragma unroll
        for (int i = 0; i < TM; i++) {
            float bv = -3.4e38f; int bi = 0;
            #pragma unroll
            for (int j = 0; j < TN / 2; j++) {
                float2 f = up2(acc[i][j]);
                int c0 = n0 + tx * TN + 2 * j;
                if (f.x > bv) { bv = f.x; bi = c0; }
                if (f.y > bv) { bv = f.y; bi = c0 + 1; }
            }
            // reduce over the 16 lanes sharing this row (lanes 0-15 / 16-31)
            #pragma unroll
            for (int off = 8; off > 0; off >>= 1) {
                float ov = __shfl_xor_sync(0xffffffffu, bv, off);
                int   oi = __shfl_xor_sync(0xffffffffu, bi, off);
                if (ov > bv || (ov == bv && oi < bi)) { bv = ov; bi = oi; }
            }
            if (tx == 0) {
                int row = ty * TM + i;
                if (bv > sval[row]) { sval[row] = bv; sidx[row] = bi; }
            }
        }
    }
    __syncthreads();
    if (t < BM) {
        g_pval[split * BPOS + m0 + t] = sval[t];
        g_pidx[split * BPOS + m0 + t] = sidx[t];
    }
}

// Combine the NSPLIT partial argmaxes (ties -> lower index == split 0)
__global__ void combine_kernel() {
    int p = blockIdx.x * blockDim.x + threadIdx.x;
    if (p >= BPOS) return;
    float v0 = g_pval[p], v1 = g_pval[BPOS + p];
    int   i0 = g_pidx[p], i1 = g_pidx[BPOS + p];
    g_ind[p] = (v1 > v0) ? i1 : i0;
}

// z_q gather + per-block squared-diff partials (deterministic tree reduce)
__global__ void zq_loss_kernel(const float* __restrict__ z,
                               const float* __restrict__ W,
                               float* __restrict__ out) {
    __shared__ float red[256];
    int e  = blockIdx.x * 256 + threadIdx.x;   // 0 .. 2097151
    int hw = e & 1023;
    int d  = (e >> 10) & 255;
    int bb = e >> 18;
    int p  = (bb << 10) | hw;
    int n  = g_ind[p];
    float w = W[n * EDIM + d];
    out[e] = w;
    float diff = w - z[e];
    red[threadIdx.x] = diff * diff;
    __syncthreads();
    #pragma unroll
    for (int s = 128; s > 0; s >>= 1) {
        if (threadIdx.x < s) red[threadIdx.x] += red[threadIdx.x + s];
        __syncthreads();
    }
    if (threadIdx.x == 0) g_losspart[blockIdx.x] = red[0];
}

// Final loss scalar: loss = (1 + 1 + 0.25) * mean_sq
__global__ void finalize_kernel(float* __restrict__ out) {
    __shared__ float red[256];
    float s = 0.0f;
    for (int i = threadIdx.x; i < 8192; i += 256) s += g_losspart[i];
    red[threadIdx.x] = s;
    __syncthreads();
    #pragma unroll
    for (int st = 128; st > 0; st >>= 1) {
        if (threadIdx.x < st) red[threadIdx.x] += red[threadIdx.x + st];
        __syncthreads();
    }
    if (threadIdx.x == 0)
        out[ZQ_ELEMS] = 2.25f * red[0] / (float)ZQ_ELEMS;
}

// ind_flat as float (assumed output packing: z_q | loss | ind_flat)
__global__ void write_ind_kernel(float* __restrict__ out) {
    int p = blockIdx.x * blockDim.x + threadIdx.x;
    if (p < BPOS) out[ZQ_ELEMS + 1 + p] = (float)g_ind[p];
}

extern "C" void kernel_launch(void* const* d_in, const int* in_sizes, int n_in,
                              void* d_out, int out_size) {
    const float* z = (const float*)d_in[0];   // (8, 256, 32, 32)
    const float* W = (const float*)d_in[1];   // (8192, 256)
    float* out = (float*)d_out;

    constexpr size_t SMEM_BYTES =
        (size_t)(EDIM * BM + BK * BSTRIDE + BM) * sizeof(float) + BM * sizeof(int);
    cudaFuncSetAttribute(gemm_argmax_kernel,
                         cudaFuncAttributeMaxDynamicSharedMemorySize,
                         (int)SMEM_BYTES);

    gemm_argmax_kernel<<<dim3(BPOS / BM, NSPLIT), THREADS, SMEM_BYTES>>>(z, W);
    combine_kernel<<<BPOS / 256, 256>>>();
    zq_loss_kernel<<<ZQ_ELEMS / 256, 256>>>(z, W, out);
    if (out_size > ZQ_ELEMS) {
        finalize_kernel<<<1, 256>>>(out);
    }
    if (out_size >= ZQ_ELEMS + 1 + BPOS) {
        write_ind_kernel<<<BPOS / 256, 256>>>(out);
    }
}

// round 3
// speedup vs baseline: 3.4670x; 3.4670x over previous
#include <cuda_runtime.h>
#include <cuda_bf16.h>
#include <cstdint>

// ---------------- problem constants ----------------
#define N_E      8192
#define EDIM     256
#define BPOS     8192          // 8 * 32 * 32 positions
#define ZQ_ELEMS 2097152       // 8 * 256 * 32 * 32

// ---------------- pass-1 tiling ----------------
#define GM       128           // positions per CTA
#define BN       128           // codes per chunk
#define NSPLIT   2
#define NCHUNK   32            // 4096 / 128 per split
#define P1THREADS 256          // 8 warps: 4m x 2n
#define CAP      64            // candidate capacity per position
#define MARGIN   1.0f

// ---------------- static device scratch ----------------
// bf16 operands, pre-swizzled (16B chunk kc stored at kc ^ (row&7))
__device__ __align__(128) __nv_bfloat16 g_Abf[64 * GM * EDIM];   // [mtile][m][k]
__device__ __align__(128) __nv_bfloat16 g_Wbf[N_E * EDIM];       // [n][k]
__device__ int g_ccnt[BPOS];
__device__ int g_cand[BPOS * CAP];
__device__ int g_ind[BPOS];
__device__ float g_losspart[8192];

// ---------------- helpers ----------------
__device__ __forceinline__ uint32_t smem_u32(const void* p) {
    uint32_t a;
    asm("{ .reg .u64 t; cvta.to.shared.u64 t, %1; cvt.u32.u64 %0, t; }" : "=r"(a) : "l"(p));
    return a;
}
__device__ __forceinline__ uint32_t encf(float f) {
    uint32_t u = __float_as_uint(f);
    return (u & 0x80000000u) ? ~u : (u | 0x80000000u);
}
__device__ __forceinline__ float decf(uint32_t u) {
    return (u & 0x80000000u) ? __uint_as_float(u & 0x7FFFFFFFu) : __uint_as_float(~u);
}

#define LDSM4(r0, r1, r2, r3, addr) \
    asm volatile("ldmatrix.sync.aligned.m8n8.x4.shared.b16 {%0,%1,%2,%3},[%4];" \
        : "=r"(r0), "=r"(r1), "=r"(r2), "=r"(r3) : "r"(addr))

#define MMA16816(c0, c1, c2, c3, a0, a1, a2, a3, b0, b1) \
    asm volatile("mma.sync.aligned.m16n8k16.row.col.f32.bf16.bf16.f32 " \
        "{%0,%1,%2,%3},{%4,%5,%6,%7},{%8,%9},{%0,%1,%2,%3};" \
        : "+f"(c0), "+f"(c1), "+f"(c2), "+f"(c3) \
        : "r"(a0), "r"(a1), "r"(a2), "r"(a3), "r"(b0), "r"(b1))

#define CP16(dst, src) \
    asm volatile("cp.async.cg.shared.global [%0], [%1], 16;" :: "r"(dst), "l"(src))
#define CP_COMMIT() asm volatile("cp.async.commit_group;" ::: "memory")
#define CP_WAIT1()  asm volatile("cp.async.wait_group 1;" ::: "memory")
#define CP_WAIT0()  asm volatile("cp.async.wait_group 0;" ::: "memory")

// =====================================================================
// Convert kernels: fp32 -> bf16, pre-swizzled ((kc ^ (row&7)) in 16B units)
// =====================================================================
__global__ void conv_W_kernel(const float* __restrict__ W) {
    int c  = blockIdx.x * blockDim.x + threadIdx.x;   // 0..262143 (16B chunks)
    int n  = c >> 5;
    int kc = c & 31;
    const float4* src = (const float4*)(W + (size_t)n * EDIM + kc * 8);
    float4 v0 = src[0], v1 = src[1];
    uint4 o;
    o.x = __nv_bfloat162_raw(__floats2bfloat162_rn(v0.x, v0.y)).x |
          ((uint32_t)__nv_bfloat162_raw(__floats2bfloat162_rn(v0.x, v0.y)).y << 16);
    // simpler reliable packing:
    __nv_bfloat162 p0 = __floats2bfloat162_rn(v0.x, v0.y);
    __nv_bfloat162 p1 = __floats2bfloat162_rn(v0.z, v0.w);
    __nv_bfloat162 p2 = __floats2bfloat162_rn(v1.x, v1.y);
    __nv_bfloat162 p3 = __floats2bfloat162_rn(v1.z, v1.w);
    o.x = *(uint32_t*)&p0; o.y = *(uint32_t*)&p1;
    o.z = *(uint32_t*)&p2; o.w = *(uint32_t*)&p3;
    uint32_t off = (uint32_t)n * 512 + ((uint32_t)(kc ^ (n & 7)) << 4);
    *(uint4*)((char*)g_Wbf + off) = o;
}

// z (8,256,32,32) -> g_Abf[mtile][m][k] bf16, transposed via smem
__global__ void conv_A_kernel(const float* __restrict__ z) {
    __shared__ float s[32][GM + 1];
    int tile = blockIdx.x;             // mt*8 + ks
    int mt   = tile >> 3;
    int ks   = tile & 7;
    int m0   = mt * GM;
    int b    = m0 >> 10;
    int hw0  = m0 & 1023;
    int t    = threadIdx.x;
    #pragma unroll
    for (int r = 0; r < 16; r++) {
        int idx = t + r * 256;
        int kk  = idx >> 7;
        int mm  = idx & 127;
        s[kk][mm] = z[(size_t)b * (EDIM * 1024) + (size_t)(ks * 32 + kk) * 1024 + hw0 + mm];
    }
    __syncthreads();
    int m    = t & 127;
    int half = t >> 7;
    #pragma unroll
    for (int q = 0; q < 2; q++) {
        int kcl = half * 2 + q;        // 0..3 (16B chunk within this 32-k slice)
        uint4 o;
        uint32_t* op = (uint32_t*)&o;
        #pragma unroll
        for (int pp = 0; pp < 4; pp++) {
            int kl = kcl * 8 + pp * 2;
            __nv_bfloat162 pr = __floats2bfloat162_rn(s[kl][m], s[kl + 1][m]);
            op[pp] = *(uint32_t*)&pr;
        }
        int kc = ks * 4 + kcl;         // global 16B chunk 0..31
        uint32_t off = (uint32_t)mt * 65536 + (uint32_t)m * 512
                     + ((uint32_t)(kc ^ (m & 7)) << 4);
        *(uint4*)((char*)g_Abf + off) = o;
    }
}

__global__ void reset_kernel() {
    int p = blockIdx.x * blockDim.x + threadIdx.x;
    if (p < BPOS) g_ccnt[p] = 0;
}

// =====================================================================
// Pass 1: bf16 mma.sync GEMM + per-chunk max/candidate collection
// grid (64 mtiles, 2 splits) x 256 threads
// smem: pmax[128] u32 @0, A 64KB @1024, B0 @1024+64K, B1 @1024+128K
// =====================================================================
#define P1_SMEM (1024 + 3 * 65536)

__global__ void __launch_bounds__(P1THREADS, 1)
pass1_kernel() {
    extern __shared__ char dsm[];
    uint32_t sbase = smem_u32(dsm);
    uint32_t spmax = sbase;
    uint32_t smA   = sbase + 1024;
    uint32_t smB0  = sbase + 1024 + 65536;

    const int t     = threadIdx.x;
    const int lane  = t & 31;
    const int w     = t >> 5;
    const int wm    = w & 3;           // m-strip (32 rows)
    const int wn    = w >> 2;          // n-half (64 cols)
    const int mtile = blockIdx.x;
    const int split = blockIdx.y;

    uint32_t* pmax = (uint32_t*)dsm;
    if (t < GM) pmax[t] = encf(-3.4e38f);

    // prologue: A tile (64KB) + chunk 0 (64KB), one commit group
    {
        const char* srcA = (const char*)g_Abf + (size_t)mtile * 65536;
        #pragma unroll
        for (int i = 0; i < 16; i++) {
            uint32_t off = (uint32_t)(t + i * 256) * 16;
            CP16(smA + off, srcA + off);
        }
        const char* srcB = (const char*)g_Wbf + (size_t)(split * 4096) * 512;
        #pragma unroll
        for (int i = 0; i < 16; i++) {
            uint32_t off = (uint32_t)(t + i * 256) * 16;
            CP16(smB0 + off, srcB + off);
        }
        CP_COMMIT();
    }

    // per-lane ldmatrix bases
    const int lane7 = lane & 7;
    const int a_m   = wm * 32 + lane7 + (lane & 8);          // + mt*16 later
    const int a_ksl = (lane >> 4) & 1;
    const uint32_t aBase0 = smA + (uint32_t)a_m * 512;
    const uint32_t aBase1 = smA + (uint32_t)(a_m + 16) * 512;
    const int b_nl  = wn * 64 + lane7 + ((lane >> 4) & 1) * 8; // + ntp*16 later
    const int b_ksl = (lane >> 3) & 1;

    for (int cn = 0; cn < NCHUNK; cn++) {
        if (cn < NCHUNK - 1) {
            uint32_t smBn = smB0 + (uint32_t)((cn + 1) & 1) * 65536;
            const char* srcB = (const char*)g_Wbf
                             + (size_t)(split * 4096 + (cn + 1) * BN) * 512;
            #pragma unroll
            for (int i = 0; i < 16; i++) {
                uint32_t off = (uint32_t)(t + i * 256) * 16;
                CP16(smBn + off, srcB + off);
            }
            CP_COMMIT();
            CP_WAIT1();
        } else {
            CP_WAIT0();
        }
        __syncthreads();

        const uint32_t smBc = smB0 + (uint32_t)(cn & 1) * 65536;
        float acc[2][8][4];
        #pragma unroll
        for (int i = 0; i < 2; i++)
            #pragma unroll
            for (int j = 0; j < 8; j++)
                #pragma unroll
                for (int r = 0; r < 4; r++) acc[i][j][r] = 0.0f;

        #pragma unroll
        for (int ks = 0; ks < 16; ks++) {
            uint32_t a0, a1, a2, a3, c0, c1, c2, c3;
            uint32_t aoff = (uint32_t)(((2 * ks + a_ksl) ^ lane7) << 4);
            LDSM4(a0, a1, a2, a3, aBase0 + aoff);
            LDSM4(c0, c1, c2, c3, aBase1 + aoff);
            uint32_t boff = (uint32_t)(((2 * ks + b_ksl) ^ lane7) << 4);
            #pragma unroll
            for (int ntp = 0; ntp < 4; ntp++) {
                uint32_t r0, r1, r2, r3;
                uint32_t baddr = smBc + (uint32_t)(b_nl + ntp * 16) * 512 + boff;
                LDSM4(r0, r1, r2, r3, baddr);
                MMA16816(acc[0][2*ntp][0], acc[0][2*ntp][1], acc[0][2*ntp][2], acc[0][2*ntp][3],
                         a0, a1, a2, a3, r0, r1);
                MMA16816(acc[0][2*ntp+1][0], acc[0][2*ntp+1][1], acc[0][2*ntp+1][2], acc[0][2*ntp+1][3],
                         a0, a1, a2, a3, r2, r3);
                MMA16816(acc[1][2*ntp][0], acc[1][2*ntp][1], acc[1][2*ntp][2], acc[1][2*ntp][3],
                         c0, c1, c2, c3, r0, r1);
                MMA16816(acc[1][2*ntp+1][0], acc[1][2*ntp+1][1], acc[1][2*ntp+1][2], acc[1][2*ntp+1][3],
                         c0, c1, c2, c3, r2, r3);
            }
        }

        // epilogue: update per-row max, then collect candidates
        const int rbase = wm * 32 + (lane >> 2);
        #pragma unroll
        for (int mt = 0; mt < 2; mt++) {
            #pragma unroll
            for (int h = 0; h < 2; h++) {
                int row = rbase + mt * 16 + 8 * h;
                float mx = -3.4e38f;
                #pragma unroll
                for (int nt = 0; nt < 8; nt++) {
                    mx = fmaxf(mx, acc[mt][nt][2 * h]);
                    mx = fmaxf(mx, acc[mt][nt][2 * h + 1]);
                }
                atomicMax(&pmax[row], encf(mx));
            }
        }
        #pragma unroll
        for (int mt = 0; mt < 2; mt++) {
            #pragma unroll
            for (int h = 0; h < 2; h++) {
                int row = rbase + mt * 16 + 8 * h;
                float thr = decf(pmax[row]) - MARGIN;
                int p = mtile * GM + row;
                #pragma unroll
                for (int nt = 0; nt < 8; nt++) {
                    #pragma unroll
                    for (int cc = 0; cc < 2; cc++) {
                        float v = acc[mt][nt][2 * h + cc];
                        if (v >= thr) {
                            int n_abs = split * 4096 + cn * BN + wn * 64
                                      + nt * 8 + 2 * (lane & 3) + cc;
                            int slot = atomicAdd(&g_ccnt[p], 1);
                            if (slot < CAP) g_cand[p * CAP + slot] = n_abs;
                        }
                    }
                }
            }
        }
        __syncthreads();   // buffer reuse + epilogue done
    }
}

// =====================================================================
// Pass 2: exact fp32 argmax over candidate set (one warp per position)
// =====================================================================
__global__ void pass2_kernel(const float* __restrict__ z,
                             const float* __restrict__ W) {
    int p = blockIdx.x * 8 + (threadIdx.x >> 5);
    if (p >= BPOS) return;
    int lane = threadIdx.x & 31;
    int b  = p >> 10;
    int hw = p & 1023;
    float zr[8];
    #pragma unroll
    for (int j = 0; j < 8; j++)
        zr[j] = z[(size_t)b * (EDIM * 1024) + (size_t)(lane * 8 + j) * 1024 + hw];

    int cnt = g_ccnt[p];
    float best_v = -3.4e38f;
    int   best_i = 0x7FFFFFFF;

    if (cnt <= CAP) {
        for (int c = 0; c < cnt; c++) {
            int n = g_cand[p * CAP + c];
            const float* wr = W + (size_t)n * EDIM + lane * 8;
            float s = 0.0f;
            #pragma unroll
            for (int j = 0; j < 8; j++) s = fmaf(zr[j], wr[j], s);
            #pragma unroll
            for (int off = 16; off > 0; off >>= 1)
                s += __shfl_xor_sync(0xffffffffu, s, off);
            if (s > best_v || (s == best_v && n < best_i)) { best_v = s; best_i = n; }
        }
    } else {
        // overflow fallback: exact scan of all codes (rare / never expected)
        for (int n = 0; n < N_E; n++) {
            const float* wr = W + (size_t)n * EDIM + lane * 8;
            float s = 0.0f;
            #pragma unroll
            for (int j = 0; j < 8; j++) s = fmaf(zr[j], wr[j], s);
            #pragma unroll
            for (int off = 16; off > 0; off >>= 1)
                s += __shfl_xor_sync(0xffffffffu, s, off);
            if (s > best_v) { best_v = s; best_i = n; }
        }
    }
    if (lane == 0) g_ind[p] = best_i;
}

// =====================================================================
// downstream (unchanged from R1, which passed with rel_err 0.0)
// =====================================================================
__global__ void zq_loss_kernel(const float* __restrict__ z,
                               const float* __restrict__ W,
                               float* __restrict__ out) {
    __shared__ float red[256];
    int e  = blockIdx.x * 256 + threadIdx.x;
    int hw = e & 1023;
    int d  = (e >> 10) & 255;
    int bb = e >> 18;
    int p  = (bb << 10) | hw;
    int n  = g_ind[p];
    float w = W[(size_t)n * EDIM + d];
    out[e] = w;
    float diff = w - z[e];
    red[threadIdx.x] = diff * diff;
    __syncthreads();
    #pragma unroll
    for (int s = 128; s > 0; s >>= 1) {
        if (threadIdx.x < s) red[threadIdx.x] += red[threadIdx.x + s];
        __syncthreads();
    }
    if (threadIdx.x == 0) g_losspart[blockIdx.x] = red[0];
}

__global__ void finalize_kernel(float* __restrict__ out) {
    __shared__ float red[256];
    float s = 0.0f;
    for (int i = threadIdx.x; i < 8192; i += 256) s += g_losspart[i];
    red[threadIdx.x] = s;
    __syncthreads();
    #pragma unroll
    for (int st = 128; st > 0; st >>= 1) {
        if (threadIdx.x < st) red[threadIdx.x] += red[threadIdx.x + st];
        __syncthreads();
    }
    if (threadIdx.x == 0)
        out[ZQ_ELEMS] = 2.25f * red[0] / (float)ZQ_ELEMS;
}

__global__ void write_ind_kernel(float* __restrict__ out) {
    int p = blockIdx.x * blockDim.x + threadIdx.x;
    if (p < BPOS) out[ZQ_ELEMS + 1 + p] = (float)g_ind[p];
}

// =====================================================================
extern "C" void kernel_launch(void* const* d_in, const int* in_sizes, int n_in,
                              void* d_out, int out_size) {
    const float* z = (const float*)d_in[0];   // (8, 256, 32, 32)
    const float* W = (const float*)d_in[1];   // (8192, 256)
    float* out = (float*)d_out;

    cudaFuncSetAttribute(pass1_kernel,
                         cudaFuncAttributeMaxDynamicSharedMemorySize, P1_SMEM);

    reset_kernel<<<BPOS / 256, 256>>>();
    conv_W_kernel<<<1024, 256>>>(W);
    conv_A_kernel<<<512, 256>>>(z);
    pass1_kernel<<<dim3(64, NSPLIT), P1THREADS, P1_SMEM>>>();
    pass2_kernel<<<BPOS / 8, 256>>>(z, W);
    zq_loss_kernel<<<ZQ_ELEMS / 256, 256>>>(z, W, out);
    if (out_size > ZQ_ELEMS) {
        finalize_kernel<<<1, 256>>>(out);
    }
    if (out_size >= ZQ_ELEMS + 1 + BPOS) {
        write_ind_kernel<<<BPOS / 256, 256>>>(out);
    }
}

// round 4
// speedup vs baseline: 3.9530x; 1.1402x over previous
#include <cuda_runtime.h>
#include <cuda_bf16.h>
#include <cstdint>

// ---------------- problem constants ----------------
#define N_E      8192
#define EDIM     256
#define BPOS     8192          // 8 * 32 * 32 positions
#define ZQ_ELEMS 2097152       // 8 * 256 * 32 * 32

// ---------------- pass-1 tiling ----------------
#define GM       128           // positions per CTA
#define BN       128           // codes per chunk
#define NSPLIT   2
#define NCHUNK   32            // 4096 / 128 per split
#define P1THREADS 512          // 16 warps: 4m x 4n
#define CAP      64            // candidate capacity per position
#define MARGIN   1.0f

// ---------------- static device scratch ----------------
// bf16 operands, pre-swizzled (16B chunk kc stored at kc ^ (row&7))
__device__ __align__(128) __nv_bfloat16 g_Abf[64 * GM * EDIM];   // [mtile][m][k]
__device__ __align__(128) __nv_bfloat16 g_Wbf[N_E * EDIM];       // [n][k]
__device__ int g_ccnt[BPOS];
__device__ int g_cand[BPOS * CAP];
__device__ int g_ind[BPOS];
__device__ float g_losspart[8192];

// ---------------- helpers ----------------
__device__ __forceinline__ uint32_t smem_u32(const void* p) {
    uint32_t a;
    asm("{ .reg .u64 t; cvta.to.shared.u64 t, %1; cvt.u32.u64 %0, t; }" : "=r"(a) : "l"(p));
    return a;
}
__device__ __forceinline__ uint32_t encf(float f) {
    uint32_t u = __float_as_uint(f);
    return (u & 0x80000000u) ? ~u : (u | 0x80000000u);
}
__device__ __forceinline__ float decf(uint32_t u) {
    return (u & 0x80000000u) ? __uint_as_float(u & 0x7FFFFFFFu) : __uint_as_float(~u);
}

#define LDSM4(r0, r1, r2, r3, addr) \
    asm volatile("ldmatrix.sync.aligned.m8n8.x4.shared.b16 {%0,%1,%2,%3},[%4];" \
        : "=r"(r0), "=r"(r1), "=r"(r2), "=r"(r3) : "r"(addr))

#define MMA16816(c0, c1, c2, c3, a0, a1, a2, a3, b0, b1) \
    asm volatile("mma.sync.aligned.m16n8k16.row.col.f32.bf16.bf16.f32 " \
        "{%0,%1,%2,%3},{%4,%5,%6,%7},{%8,%9},{%0,%1,%2,%3};" \
        : "+f"(c0), "+f"(c1), "+f"(c2), "+f"(c3) \
        : "r"(a0), "r"(a1), "r"(a2), "r"(a3), "r"(b0), "r"(b1))

#define CP16(dst, src) \
    asm volatile("cp.async.cg.shared.global [%0], [%1], 16;" :: "r"(dst), "l"(src))
#define CP_COMMIT() asm volatile("cp.async.commit_group;" ::: "memory")
#define CP_WAIT1()  asm volatile("cp.async.wait_group 1;" ::: "memory")
#define CP_WAIT0()  asm volatile("cp.async.wait_group 0;" ::: "memory")

// =====================================================================
// Fused prep: blocks [0,1024) convert W, [1024,1536) convert/transpose A,
// [1536,1568) reset candidate counters.
// =====================================================================
__global__ void prep_kernel(const float* __restrict__ z,
                            const float* __restrict__ W) {
    __shared__ float s[32][GM + 1];
    int blk = blockIdx.x;
    int t   = threadIdx.x;

    if (blk < 1024) {
        // ---- W -> bf16, swizzled ----
        int c  = blk * 256 + t;            // 0..262143 (16B chunks)
        int n  = c >> 5;
        int kc = c & 31;
        const float4* src = (const float4*)(W + (size_t)n * EDIM + kc * 8);
        float4 v0 = src[0], v1 = src[1];
        __nv_bfloat162 p0 = __floats2bfloat162_rn(v0.x, v0.y);
        __nv_bfloat162 p1 = __floats2bfloat162_rn(v0.z, v0.w);
        __nv_bfloat162 p2 = __floats2bfloat162_rn(v1.x, v1.y);
        __nv_bfloat162 p3 = __floats2bfloat162_rn(v1.z, v1.w);
        uint4 o;
        o.x = *(uint32_t*)&p0; o.y = *(uint32_t*)&p1;
        o.z = *(uint32_t*)&p2; o.w = *(uint32_t*)&p3;
        uint32_t off = (uint32_t)n * 512 + ((uint32_t)(kc ^ (n & 7)) << 4);
        *(uint4*)((char*)g_Wbf + off) = o;
    } else if (blk < 1536) {
        // ---- z -> A bf16, transposed + swizzled ----
        int tile = blk - 1024;             // mt*8 + ks
        int mt   = tile >> 3;
        int ks   = tile & 7;
        int m0   = mt * GM;
        int b    = m0 >> 10;
        int hw0  = m0 & 1023;
        #pragma unroll
        for (int r = 0; r < 16; r++) {
            int idx = t + r * 256;
            int kk  = idx >> 7;
            int mm  = idx & 127;
            s[kk][mm] = z[(size_t)b * (EDIM * 1024) + (size_t)(ks * 32 + kk) * 1024 + hw0 + mm];
        }
        __syncthreads();
        int m    = t & 127;
        int half = t >> 7;
        #pragma unroll
        for (int q = 0; q < 2; q++) {
            int kcl = half * 2 + q;
            uint4 o;
            uint32_t* op = (uint32_t*)&o;
            #pragma unroll
            for (int pp = 0; pp < 4; pp++) {
                int kl = kcl * 8 + pp * 2;
                __nv_bfloat162 pr = __floats2bfloat162_rn(s[kl][m], s[kl + 1][m]);
                op[pp] = *(uint32_t*)&pr;
            }
            int kc = ks * 4 + kcl;
            uint32_t off = (uint32_t)mt * 65536 + (uint32_t)m * 512
                         + ((uint32_t)(kc ^ (m & 7)) << 4);
            *(uint4*)((char*)g_Abf + off) = o;
        }
    } else {
        int p = (blk - 1536) * 256 + t;
        if (p < BPOS) g_ccnt[p] = 0;
    }
}

// =====================================================================
// Pass 1: bf16 mma.sync GEMM + per-chunk max/candidate collection
// grid (64 mtiles, 2 splits) x 512 threads (16 warps, 4m x 4n)
// smem: pmax[128] u32 @0, A 64KB @1024, B0 @1024+64K, B1 @1024+128K
// =====================================================================
#define P1_SMEM (1024 + 3 * 65536)

__global__ void __launch_bounds__(P1THREADS, 1)
pass1_kernel() {
    extern __shared__ char dsm[];
    uint32_t sbase = smem_u32(dsm);
    uint32_t smA   = sbase + 1024;
    uint32_t smB0  = sbase + 1024 + 65536;

    const int t     = threadIdx.x;
    const int lane  = t & 31;
    const int w     = t >> 5;
    const int wm    = w & 3;           // m-strip (32 rows)
    const int wn    = w >> 2;          // n-quarter (32 cols)
    const int mtile = blockIdx.x;
    const int split = blockIdx.y;

    uint32_t* pmax = (uint32_t*)dsm;
    if (t < GM) pmax[t] = encf(-3.4e38f);

    // prologue: A tile (64KB) + B chunk 0 (64KB), one commit group
    {
        const char* srcA = (const char*)g_Abf + (size_t)mtile * 65536;
        #pragma unroll
        for (int i = 0; i < 8; i++) {
            uint32_t off = (uint32_t)(t + i * 512) * 16;
            CP16(smA + off, srcA + off);
        }
        const char* srcB = (const char*)g_Wbf + (size_t)(split * 4096) * 512;
        #pragma unroll
        for (int i = 0; i < 8; i++) {
            uint32_t off = (uint32_t)(t + i * 512) * 16;
            CP16(smB0 + off, srcB + off);
        }
        CP_COMMIT();
    }

    // per-lane ldmatrix bases
    const int lane7 = lane & 7;
    const int a_m   = wm * 32 + lane7 + (lane & 8);
    const int a_ksl = (lane >> 4) & 1;
    const uint32_t aBase0 = smA + (uint32_t)a_m * 512;
    const uint32_t aBase1 = smA + (uint32_t)(a_m + 16) * 512;
    const int b_nl  = wn * 32 + lane7 + ((lane >> 4) & 1) * 8;
    const int b_ksl = (lane >> 3) & 1;

    for (int cn = 0; cn < NCHUNK; cn++) {
        if (cn < NCHUNK - 1) {
            uint32_t smBn = smB0 + (uint32_t)((cn + 1) & 1) * 65536;
            const char* srcB = (const char*)g_Wbf
                             + (size_t)(split * 4096 + (cn + 1) * BN) * 512;
            #pragma unroll
            for (int i = 0; i < 8; i++) {
                uint32_t off = (uint32_t)(t + i * 512) * 16;
                CP16(smBn + off, srcB + off);
            }
            CP_COMMIT();
            CP_WAIT1();
        } else {
            CP_WAIT0();
        }
        __syncthreads();

        const uint32_t smBc = smB0 + (uint32_t)(cn & 1) * 65536;
        float acc[2][4][4];
        #pragma unroll
        for (int i = 0; i < 2; i++)
            #pragma unroll
            for (int j = 0; j < 4; j++)
                #pragma unroll
                for (int r = 0; r < 4; r++) acc[i][j][r] = 0.0f;

        #pragma unroll
        for (int ks = 0; ks < 16; ks++) {
            uint32_t a0, a1, a2, a3, c0, c1, c2, c3;
            uint32_t aoff = (uint32_t)(((2 * ks + a_ksl) ^ lane7) << 4);
            LDSM4(a0, a1, a2, a3, aBase0 + aoff);
            LDSM4(c0, c1, c2, c3, aBase1 + aoff);
            uint32_t boff = (uint32_t)(((2 * ks + b_ksl) ^ lane7) << 4);
            #pragma unroll
            for (int ntp = 0; ntp < 2; ntp++) {
                uint32_t r0, r1, r2, r3;
                uint32_t baddr = smBc + (uint32_t)(b_nl + ntp * 16) * 512 + boff;
                LDSM4(r0, r1, r2, r3, baddr);
                MMA16816(acc[0][2*ntp][0], acc[0][2*ntp][1], acc[0][2*ntp][2], acc[0][2*ntp][3],
                         a0, a1, a2, a3, r0, r1);
                MMA16816(acc[0][2*ntp+1][0], acc[0][2*ntp+1][1], acc[0][2*ntp+1][2], acc[0][2*ntp+1][3],
                         a0, a1, a2, a3, r2, r3);
                MMA16816(acc[1][2*ntp][0], acc[1][2*ntp][1], acc[1][2*ntp][2], acc[1][2*ntp][3],
                         c0, c1, c2, c3, r0, r1);
                MMA16816(acc[1][2*ntp+1][0], acc[1][2*ntp+1][1], acc[1][2*ntp+1][2], acc[1][2*ntp+1][3],
                         c0, c1, c2, c3, r2, r3);
            }
        }

        // epilogue: update per-row max, then collect candidates
        const int rbase = wm * 32 + (lane >> 2);
        #pragma unroll
        for (int mt = 0; mt < 2; mt++) {
            #pragma unroll
            for (int h = 0; h < 2; h++) {
                int row = rbase + mt * 16 + 8 * h;
                float mx = -3.4e38f;
                #pragma unroll
                for (int nt = 0; nt < 4; nt++) {
                    mx = fmaxf(mx, acc[mt][nt][2 * h]);
                    mx = fmaxf(mx, acc[mt][nt][2 * h + 1]);
                }
                atomicMax(&pmax[row], encf(mx));
            }
        }
        #pragma unroll
        for (int mt = 0; mt < 2; mt++) {
            #pragma unroll
            for (int h = 0; h < 2; h++) {
                int row = rbase + mt * 16 + 8 * h;
                float thr = decf(pmax[row]) - MARGIN;
                int p = mtile * GM + row;
                #pragma unroll
                for (int nt = 0; nt < 4; nt++) {
                    #pragma unroll
                    for (int cc = 0; cc < 2; cc++) {
                        float v = acc[mt][nt][2 * h + cc];
                        if (v >= thr) {
                            int n_abs = split * 4096 + cn * BN + wn * 32
                                      + nt * 8 + 2 * (lane & 3) + cc;
                            int slot = atomicAdd(&g_ccnt[p], 1);
                            if (slot < CAP) g_cand[p * CAP + slot] = n_abs;
                        }
                    }
                }
            }
        }
        __syncthreads();   // buffer reuse + epilogue done
    }
}

// =====================================================================
// Pass 2: exact fp32 argmax over candidate set (one warp per position)
// =====================================================================
__global__ void pass2_kernel(const float* __restrict__ z,
                             const float* __restrict__ W) {
    int p = blockIdx.x * 8 + (threadIdx.x >> 5);
    if (p >= BPOS) return;
    int lane = threadIdx.x & 31;
    int b  = p >> 10;
    int hw = p & 1023;
    float zr[8];
    #pragma unroll
    for (int j = 0; j < 8; j++)
        zr[j] = z[(size_t)b * (EDIM * 1024) + (size_t)(lane * 8 + j) * 1024 + hw];

    int cnt = g_ccnt[p];
    float best_v = -3.4e38f;
    int   best_i = 0x7FFFFFFF;

    if (cnt <= CAP) {
        for (int c = 0; c < cnt; c++) {
            int n = g_cand[p * CAP + c];
            const float* wr = W + (size_t)n * EDIM + lane * 8;
            float s = 0.0f;
            #pragma unroll
            for (int j = 0; j < 8; j++) s = fmaf(zr[j], wr[j], s);
            #pragma unroll
            for (int off = 16; off > 0; off >>= 1)
                s += __shfl_xor_sync(0xffffffffu, s, off);
            if (s > best_v || (s == best_v && n < best_i)) { best_v = s; best_i = n; }
        }
    } else {
        // overflow fallback: exact scan of all codes (never expected)
        for (int n = 0; n < N_E; n++) {
            const float* wr = W + (size_t)n * EDIM + lane * 8;
            float s = 0.0f;
            #pragma unroll
            for (int j = 0; j < 8; j++) s = fmaf(zr[j], wr[j], s);
            #pragma unroll
            for (int off = 16; off > 0; off >>= 1)
                s += __shfl_xor_sync(0xffffffffu, s, off);
            if (s > best_v) { best_v = s; best_i = n; }
        }
    }
    if (lane == 0) g_ind[p] = best_i;
}

// =====================================================================
// downstream
// =====================================================================
__global__ void zq_loss_kernel(const float* __restrict__ z,
                               const float* __restrict__ W,
                               float* __restrict__ out) {
    __shared__ float red[8];
    int e  = blockIdx.x * 256 + threadIdx.x;
    int hw = e & 1023;
    int d  = (e >> 10) & 255;
    int bb = e >> 18;
    int p  = (bb << 10) | hw;
    int n  = g_ind[p];
    float w = W[(size_t)n * EDIM + d];
    out[e] = w;
    float diff = w - z[e];
    float s = diff * diff;
    #pragma unroll
    for (int off = 16; off > 0; off >>= 1)
        s += __shfl_xor_sync(0xffffffffu, s, off);
    if ((threadIdx.x & 31) == 0) red[threadIdx.x >> 5] = s;
    __syncthreads();
    if (threadIdx.x < 8) {
        float v = red[threadIdx.x];
        #pragma unroll
        for (int off = 4; off > 0; off >>= 1)
            v += __shfl_xor_sync(0xffu, v, off);
        if (threadIdx.x == 0) g_losspart[blockIdx.x] = v;
    }
}

__global__ void finalize_kernel(float* __restrict__ out) {
    __shared__ float red[8];
    float s = 0.0f;
    for (int i = threadIdx.x; i < 8192; i += 256) s += g_losspart[i];
    #pragma unroll
    for (int off = 16; off > 0; off >>= 1)
        s += __shfl_xor_sync(0xffffffffu, s, off);
    if ((threadIdx.x & 31) == 0) red[threadIdx.x >> 5] = s;
    __syncthreads();
    if (threadIdx.x < 8) {
        float v = red[threadIdx.x];
        #pragma unroll
        for (int off = 4; off > 0; off >>= 1)
            v += __shfl_xor_sync(0xffu, v, off);
        if (threadIdx.x == 0)
            out[ZQ_ELEMS] = 2.25f * v / (float)ZQ_ELEMS;
    }
}

__global__ void write_ind_kernel(float* __restrict__ out) {
    int p = blockIdx.x * blockDim.x + threadIdx.x;
    if (p < BPOS) out[ZQ_ELEMS + 1 + p] = (float)g_ind[p];
}

// =====================================================================
extern "C" void kernel_launch(void* const* d_in, const int* in_sizes, int n_in,
                              void* d_out, int out_size) {
    const float* z = (const float*)d_in[0];   // (8, 256, 32, 32)
    const float* W = (const float*)d_in[1];   // (8192, 256)
    float* out = (float*)d_out;

    cudaFuncSetAttribute(pass1_kernel,
                         cudaFuncAttributeMaxDynamicSharedMemorySize, P1_SMEM);

    prep_kernel<<<1568, 256>>>(z, W);
    pass1_kernel<<<dim3(64, NSPLIT), P1THREADS, P1_SMEM>>>();
    pass2_kernel<<<BPOS / 8, 256>>>(z, W);
    zq_loss_kernel<<<ZQ_ELEMS / 256, 256>>>(z, W, out);
    if (out_size > ZQ_ELEMS) {
        finalize_kernel<<<1, 256>>>(out);
    }
    if (out_size >= ZQ_ELEMS + 1 + BPOS) {
        write_ind_kernel<<<BPOS / 256, 256>>>(out);
    }
}